// round 1
// baseline (speedup 1.0000x reference)
#include <cuda_runtime.h>

// Problem constants (fixed by the reference)
#define BB 8
#define LL 1024
#define DD 512
#define HD 4096       // H*D = 8*512
#define NC1 32        // L-chunks for input reduction
#define NKC 4         // k-chunks for vsum GEMM
#define NJC 64        // j-chunks for z GEMM

// Scratch (device globals — no allocation allowed)
__device__ float g_xpart[NC1 * BB * DD];    // 512 KB
__device__ float g_xsum [BB * DD];          // 16 KB
__device__ float g_vpart[NKC * BB * HD];    // 512 KB
__device__ float g_zpart[NJC * BB * DD];    // 1 MB
__device__ float g_z    [BB * DD];          // 16 KB

// K1: partial sum of input over L within a chunk of 32 rows.
// grid (BB, NC1), 512 threads (one per d). Coalesced 128B lines across d.
__global__ void k1_sumL(const float* __restrict__ x) {
    int b = blockIdx.x, c = blockIdx.y, d = threadIdx.x;
    const float* p = x + (size_t)b * LL * DD + (size_t)c * (LL / NC1) * DD + d;
    float s = 0.f;
#pragma unroll
    for (int i = 0; i < LL / NC1; ++i) s += p[i * DD];
    g_xpart[(c * BB + b) * DD + d] = s;
}

// K1b: reduce the 32 chunk partials -> xsum[b][d]. grid BB, 512 threads.
__global__ void k1b_xsum() {
    int b = blockIdx.x, d = threadIdx.x;
    float s = 0.f;
#pragma unroll
    for (int c = 0; c < NC1; ++c) s += g_xpart[(c * BB + b) * DD + d];
    g_xsum[b * DD + d] = s;
}

// K2: vsum partials. grid (HD/256 = 16, NKC = 4), 256 threads.
// block (jb, kc): j = jb*256+t, k in [kc*128, kc*128+128).
// Each wv element read exactly once, coalesced across t.
__global__ void k2_vsum(const float* __restrict__ wv) {
    __shared__ float xs[BB * (DD / NKC)];   // 8 x 128 = 4 KB
    int t = threadIdx.x;
    int jb = blockIdx.x, kc = blockIdx.y;
    int k0 = kc * (DD / NKC);
    for (int e = t; e < BB * (DD / NKC); e += 256) {
        int b = e / (DD / NKC), kk = e % (DD / NKC);
        xs[e] = g_xsum[b * DD + k0 + kk];
    }
    __syncthreads();

    int j = jb * 256 + t;
    float acc[BB];
#pragma unroll
    for (int b = 0; b < BB; ++b) acc[b] = 0.f;
    const float* w = wv + (size_t)k0 * HD + j;
#pragma unroll 4
    for (int kk = 0; kk < DD / NKC; ++kk) {
        float wval = w[(size_t)kk * HD];
#pragma unroll
        for (int b = 0; b < BB; ++b) acc[b] += xs[b * (DD / NKC) + kk] * wval;
    }
#pragma unroll
    for (int b = 0; b < BB; ++b)
        g_vpart[(size_t)kc * BB * HD + b * HD + j] = acc[b];
}

// K3: z partials. grid NJC = 64, 512 threads (one per output i).
// Each block handles 64 j's; vsum chunk (with +L*bv folded in) staged in shared.
__global__ void k3_zpart(const float* __restrict__ fcw, const float* __restrict__ bv) {
    __shared__ float vs[BB * (HD / NJC)];   // 8 x 64 = 2 KB
    int t = threadIdx.x;
    int jc = blockIdx.x;
    int j0 = jc * (HD / NJC);
    for (int e = t; e < BB * (HD / NJC); e += 512) {
        int b = e / (HD / NJC), jj = e % (HD / NJC);
        int j = j0 + jj;
        float s = (float)LL * bv[j];
#pragma unroll
        for (int kc = 0; kc < NKC; ++kc)
            s += g_vpart[(size_t)kc * BB * HD + b * HD + j];
        vs[e] = s;
    }
    __syncthreads();

    float acc[BB];
#pragma unroll
    for (int b = 0; b < BB; ++b) acc[b] = 0.f;
    const float* w = fcw + (size_t)j0 * DD + t;
#pragma unroll 4
    for (int jj = 0; jj < HD / NJC; ++jj) {
        float wval = w[(size_t)jj * DD];
#pragma unroll
        for (int b = 0; b < BB; ++b) acc[b] += vs[b * (HD / NJC) + jj] * wval;
    }
#pragma unroll
    for (int b = 0; b < BB; ++b)
        g_zpart[((size_t)jc * BB + b) * DD + t] = acc[b];
}

// K3b: reduce z partials + fc_b. grid BB, 512 threads.
__global__ void k3b_z(const float* __restrict__ fcb) {
    int b = blockIdx.x, i = threadIdx.x;
    float s = fcb[i];
#pragma unroll
    for (int c = 0; c < NJC; ++c) s += g_zpart[((size_t)c * BB + b) * DD + i];
    g_z[b * DD + i] = s;
}

// K4: y = LayerNorm(z[b] + x[b,l]) * g + beta. grid B*L = 8192 blocks,
// 128 threads, float4 per thread (512 floats/row).
__global__ void k4_ln(const float* __restrict__ x,
                      const float* __restrict__ lng, const float* __restrict__ lnb,
                      float* __restrict__ out) {
    int row = blockIdx.x;          // b*1024 + l
    int b = row >> 10;
    int t = threadIdx.x;

    float4 xv = reinterpret_cast<const float4*>(x)[(size_t)row * 128 + t];
    float4 zv = reinterpret_cast<const float4*>(g_z)[b * 128 + t];
    float4 y;
    y.x = xv.x + zv.x; y.y = xv.y + zv.y; y.z = xv.z + zv.z; y.w = xv.w + zv.w;

    float s = y.x + y.y + y.z + y.w;
    float q = y.x * y.x + y.y * y.y + y.z * y.z + y.w * y.w;

    // warp reduce (4 warps of 32)
#pragma unroll
    for (int o = 16; o > 0; o >>= 1) {
        s += __shfl_down_sync(0xFFFFFFFFu, s, o);
        q += __shfl_down_sync(0xFFFFFFFFu, q, o);
    }
    __shared__ float rs[4], rq[4];
    int wid = t >> 5, lane = t & 31;
    if (lane == 0) { rs[wid] = s; rq[wid] = q; }
    __syncthreads();
    float S = rs[0] + rs[1] + rs[2] + rs[3];
    float Q = rq[0] + rq[1] + rq[2] + rq[3];

    float mu  = S * (1.0f / DD);
    float var = Q * (1.0f / DD) - mu * mu;
    float inv = rsqrtf(var + 1e-5f);

    float4 gv = reinterpret_cast<const float4*>(lng)[t];
    float4 bv = reinterpret_cast<const float4*>(lnb)[t];
    float4 o;
    o.x = (y.x - mu) * inv * gv.x + bv.x;
    o.y = (y.y - mu) * inv * gv.y + bv.y;
    o.z = (y.z - mu) * inv * gv.z + bv.z;
    o.w = (y.w - mu) * inv * gv.w + bv.w;
    reinterpret_cast<float4*>(out)[(size_t)row * 128 + t] = o;
}

extern "C" void kernel_launch(void* const* d_in, const int* in_sizes, int n_in,
                              void* d_out, int out_size) {
    // metadata order: input, wq, bq, wk, bk, wv, bv, score_w, score_b,
    //                 fc_w, fc_b, ln_g, ln_b
    const float* input = (const float*)d_in[0];
    const float* wv    = (const float*)d_in[5];
    const float* bv    = (const float*)d_in[6];
    const float* fcw   = (const float*)d_in[9];
    const float* fcb   = (const float*)d_in[10];
    const float* lng   = (const float*)d_in[11];
    const float* lnb   = (const float*)d_in[12];
    float* out = (float*)d_out;

    k1_sumL <<<dim3(BB, NC1), DD>>>(input);
    k1b_xsum<<<BB, DD>>>();
    k2_vsum <<<dim3(HD / 256, NKC), 256>>>(wv);
    k3_zpart<<<NJC, DD>>>(fcw, bv);
    k3b_z   <<<BB, DD>>>(fcb);
    k4_ln   <<<BB * LL, 128>>>(input, lng, lnb, out);
}

// round 2
// speedup vs baseline: 2.0468x; 2.0468x over previous
#include <cuda_runtime.h>

#define BB 8
#define LL 1024
#define DD 512
#define HD 4096       // H*D

// Accumulators (device globals — no allocation allowed)
__device__ float g_xsum[BB * DD];      // sum over L of input   (8x512)
__device__ float g_vsum[BB * HD];      // xsum@wv + L*bv        (8x4096)
__device__ float g_z   [BB * DD];      // vsum@fc_w + fc_b      (8x512)

// K0: initialize accumulators: g_xsum=0, g_vsum=L*bv, g_z=fc_b.
// total 4096 + 32768 + 4096 = 40960 elements.
__global__ void k0_init(const float* __restrict__ bv, const float* __restrict__ fcb) {
    int i = blockIdx.x * 1024 + threadIdx.x;
    if (i < BB * DD) g_xsum[i] = 0.f;
    if (i < BB * HD) g_vsum[i] = (float)LL * bv[i & (HD - 1)];
    if (i < BB * DD) g_z[i] = fcb[i & (DD - 1)];
}

// K1: sum input over L. grid (8, 32): block (b, c) sums 32 rows, one thread
// per d (512). Coalesced; single REDG per thread at the end.
__global__ void k1_sumL(const float* __restrict__ x) {
    int b = blockIdx.x, c = blockIdx.y, d = threadIdx.x;
    const float* p = x + (size_t)b * LL * DD + (size_t)c * 32 * DD + d;
    float s = 0.f;
#pragma unroll
    for (int i = 0; i < 32; ++i) s += p[i * DD];
    atomicAdd(&g_xsum[b * DD + d], s);
}

// K2: vsum += xsum @ wv. grid (16 j-blocks x 16 k-chunks) = 256 blocks,
// 256 threads (one per j within block). Each block reads wv[k0:k0+32, j0:j0+256]
// = 32 KB, coalesced across threads.
__global__ void k2_vsum(const float* __restrict__ wv) {
    __shared__ float xs[BB * 32];          // xsum chunk, 1 KB
    int t = threadIdx.x;
    int jb = blockIdx.x, kc = blockIdx.y;
    int k0 = kc * 32;
    if (t < BB * 32) {
        int b = t >> 5, kk = t & 31;
        xs[t] = g_xsum[b * DD + k0 + kk];
    }
    __syncthreads();

    int j = jb * 256 + t;
    float acc[BB];
#pragma unroll
    for (int b = 0; b < BB; ++b) acc[b] = 0.f;
    const float* w = wv + (size_t)k0 * HD + j;
#pragma unroll 8
    for (int kk = 0; kk < 32; ++kk) {
        float wval = w[(size_t)kk * HD];
#pragma unroll
        for (int b = 0; b < BB; ++b) acc[b] += xs[b * 32 + kk] * wval;
    }
#pragma unroll
    for (int b = 0; b < BB; ++b)
        atomicAdd(&g_vsum[b * HD + j], acc[b]);
}

// K3: z += vsum @ fc_w. grid 256 blocks (j-chunks of 16), 512 threads (one
// per output i). Each block reads fc_w[j0:j0+16, :] = 32 KB, coalesced.
__global__ void k3_z(const float* __restrict__ fcw) {
    __shared__ float vs[BB * 16];          // vsum chunk, 512 B
    int t = threadIdx.x;
    int jc = blockIdx.x;
    int j0 = jc * 16;
    if (t < BB * 16) {
        int b = t >> 4, jj = t & 15;
        vs[t] = g_vsum[b * HD + j0 + jj];
    }
    __syncthreads();

    float acc[BB];
#pragma unroll
    for (int b = 0; b < BB; ++b) acc[b] = 0.f;
    const float* w = fcw + (size_t)j0 * DD + t;
#pragma unroll
    for (int jj = 0; jj < 16; ++jj) {
        float wval = w[(size_t)jj * DD];
#pragma unroll
        for (int b = 0; b < BB; ++b) acc[b] += vs[b * 16 + jj] * wval;
    }
#pragma unroll
    for (int b = 0; b < BB; ++b)
        atomicAdd(&g_z[b * DD + t], acc[b]);
}

// K4: out = LayerNorm(z[b] + x[b,l]) * g + beta. Warp-per-row: 8 warps/block,
// 1024 blocks. Each lane handles 4 float4 (16 floats) of the 512-float row.
// No __syncthreads — xor-shuffle reduction only.
__global__ void k4_ln(const float* __restrict__ x,
                      const float* __restrict__ lng, const float* __restrict__ lnb,
                      float* __restrict__ out) {
    int warp = (blockIdx.x * blockDim.x + threadIdx.x) >> 5;  // row id 0..8191
    int lane = threadIdx.x & 31;
    int b = warp >> 10;

    const float4* xp = reinterpret_cast<const float4*>(x) + (size_t)warp * 128;
    const float4* zp = reinterpret_cast<const float4*>(g_z) + b * 128;

    float4 y[4];
    float s = 0.f, q = 0.f;
#pragma unroll
    for (int i = 0; i < 4; ++i) {
        float4 xv = xp[lane + 32 * i];
        float4 zv = zp[lane + 32 * i];
        y[i].x = xv.x + zv.x; y[i].y = xv.y + zv.y;
        y[i].z = xv.z + zv.z; y[i].w = xv.w + zv.w;
        s += y[i].x + y[i].y + y[i].z + y[i].w;
        q += y[i].x * y[i].x + y[i].y * y[i].y + y[i].z * y[i].z + y[i].w * y[i].w;
    }
#pragma unroll
    for (int o = 16; o > 0; o >>= 1) {
        s += __shfl_xor_sync(0xFFFFFFFFu, s, o);
        q += __shfl_xor_sync(0xFFFFFFFFu, q, o);
    }
    float mu  = s * (1.0f / DD);
    float var = q * (1.0f / DD) - mu * mu;
    float inv = rsqrtf(var + 1e-5f);

    const float4* gp = reinterpret_cast<const float4*>(lng);
    const float4* bp = reinterpret_cast<const float4*>(lnb);
    float4* op = reinterpret_cast<float4*>(out) + (size_t)warp * 128;
#pragma unroll
    for (int i = 0; i < 4; ++i) {
        float4 gv = gp[lane + 32 * i];
        float4 be = bp[lane + 32 * i];
        float4 o;
        o.x = (y[i].x - mu) * inv * gv.x + be.x;
        o.y = (y[i].y - mu) * inv * gv.y + be.y;
        o.z = (y[i].z - mu) * inv * gv.z + be.z;
        o.w = (y[i].w - mu) * inv * gv.w + be.w;
        op[lane + 32 * i] = o;
    }
}

extern "C" void kernel_launch(void* const* d_in, const int* in_sizes, int n_in,
                              void* d_out, int out_size) {
    // metadata order: input, wq, bq, wk, bk, wv, bv, score_w, score_b,
    //                 fc_w, fc_b, ln_g, ln_b
    const float* input = (const float*)d_in[0];
    const float* wv    = (const float*)d_in[5];
    const float* bv    = (const float*)d_in[6];
    const float* fcw   = (const float*)d_in[9];
    const float* fcb   = (const float*)d_in[10];
    const float* lng   = (const float*)d_in[11];
    const float* lnb   = (const float*)d_in[12];
    float* out = (float*)d_out;

    k0_init<<<40, 1024>>>(bv, fcb);
    k1_sumL<<<dim3(BB, 32), DD>>>(input);
    k2_vsum<<<dim3(16, 16), 256>>>(wv);
    k3_z   <<<256, DD>>>(fcw);
    k4_ln  <<<BB * LL / 8, 256>>>(input, lng, lnb, out);
}